// round 11
// baseline (speedup 1.0000x reference)
#include <cuda_runtime.h>
#include <cuda_fp16.h>
#include <cstdint>

#define BWIN 4096
#define NTOK 49
#define DIM  256
#define NH   8
#define HD   32
#define MTOT (BWIN * NTOK)            /* 200704 */
#define QKV_S (BWIN * NH * NTOK * HD) /* 51380224 */

typedef unsigned long long u64;
typedef unsigned int u32;

// ---------------- device scratch (allocation-free) ----------------
// g_qkv reused as 5 fp16 planes: 0=q_hi, 1=q_lo, 2=k_hi, 3=v_hi, 4=v_lo
__device__ float g_qkv[3ULL * QKV_S];
__device__ float g_bias[NH * NTOK * NTOK];                  // [H][N][N]
__device__ __align__(16) __half g_xhi[(size_t)MTOT * DIM];
__device__ __align__(16) __half g_xlo[(size_t)MTOT * DIM];
__device__ __align__(16) __half g_ahi[(size_t)MTOT * DIM];
__device__ __align__(16) __half g_alo[(size_t)MTOT * DIM];
__device__ __align__(16) __half g_wqhi[768 * 256];
__device__ __align__(16) __half g_wphi[256 * 256];

// ---------------- helpers ----------------
__device__ __forceinline__ void split_h(float x, unsigned short& h, unsigned short& l) {
    __half hb = __float2half_rn(x);
    float r = x - __half2float(hb);
    __half lb = __float2half_rn(r);
    h = __half_as_ushort(hb);
    l = __half_as_ushort(lb);
}
__device__ __forceinline__ u32 smem_u32(const void* p) {
    u32 a;
    asm("{ .reg .u64 t; cvta.to.shared.u64 t, %1; cvt.u32.u64 %0, t; }" : "=r"(a) : "l"(p));
    return a;
}

__device__ __forceinline__ void mma16816(float* d, u32 a0, u32 a1, u32 a2, u32 a3,
                                         u32 b0, u32 b1) {
    asm volatile(
        "mma.sync.aligned.m16n8k16.row.col.f32.f16.f16.f32 "
        "{%0,%1,%2,%3}, {%4,%5,%6,%7}, {%8,%9}, {%0,%1,%2,%3};"
        : "+f"(d[0]), "+f"(d[1]), "+f"(d[2]), "+f"(d[3])
        : "r"(a0), "r"(a1), "r"(a2), "r"(a3), "r"(b0), "r"(b1));
}

#define LDSM_X4(r0, r1, r2, r3, addr) \
    asm volatile("ldmatrix.sync.aligned.m8n8.x4.shared.b16 {%0,%1,%2,%3}, [%4];" \
        : "=r"(r0), "=r"(r1), "=r"(r2), "=r"(r3) : "r"(addr))
#define LDSM_X4T(r0, r1, r2, r3, addr) \
    asm volatile("ldmatrix.sync.aligned.m8n8.x4.trans.shared.b16 {%0,%1,%2,%3}, [%4];" \
        : "=r"(r0), "=r"(r1), "=r"(r2), "=r"(r3) : "r"(addr))

#define CP_ASYNC16(s, g) \
    asm volatile("cp.async.cg.shared.global [%0], [%1], 16;" :: "r"(s), "l"(g))
#define CP_COMMIT() asm volatile("cp.async.commit_group;" ::: "memory")
#define CP_WAITG(n) asm volatile("cp.async.wait_group %0;" :: "n"(n) : "memory")

// ---------------- kernel: bias gather ----------------
__global__ void bias_kernel(const float* __restrict__ table, const int* __restrict__ rel) {
    int idx = blockIdx.x * 256 + threadIdx.x;
    if (idx < NH * NTOK * NTOK) {
        int h = idx / (NTOK * NTOK);
        int nm = idx - h * (NTOK * NTOK);
        g_bias[idx] = table[rel[nm] * NH + h];
    }
}

// ---------------- kernels: fp32 -> fp16 hi/lo ----------------
__global__ void conv_x(const float* __restrict__ x) {
    size_t i = (size_t)blockIdx.x * 256 + threadIdx.x;
    if (i < (size_t)MTOT * DIM / 4) {
        float4 v = ((const float4*)x)[i];
        unsigned short h0, h1, h2, h3, l0, l1, l2, l3;
        split_h(v.x, h0, l0); split_h(v.y, h1, l1);
        split_h(v.z, h2, l2); split_h(v.w, h3, l3);
        ((uint2*)g_xhi)[i] = make_uint2((u32)h0 | ((u32)h1 << 16), (u32)h2 | ((u32)h3 << 16));
        ((uint2*)g_xlo)[i] = make_uint2((u32)l0 | ((u32)l1 << 16), (u32)l2 | ((u32)l3 << 16));
    }
}
__global__ void conv_w(const float* __restrict__ wq, const float* __restrict__ wp) {
    int i = blockIdx.x * 256 + threadIdx.x;
    const int nq4 = 768 * 256 / 4;
    const int np4 = 256 * 256 / 4;
    if (i < nq4) {
        float4 v = ((const float4*)wq)[i];
        ((uint2*)g_wqhi)[i] = make_uint2(
            (u32)__half_as_ushort(__float2half_rn(v.x)) | ((u32)__half_as_ushort(__float2half_rn(v.y)) << 16),
            (u32)__half_as_ushort(__float2half_rn(v.z)) | ((u32)__half_as_ushort(__float2half_rn(v.w)) << 16));
    } else if (i < nq4 + np4) {
        int j = i - nq4;
        float4 v = ((const float4*)wp)[j];
        ((uint2*)g_wphi)[j] = make_uint2(
            (u32)__half_as_ushort(__float2half_rn(v.x)) | ((u32)__half_as_ushort(__float2half_rn(v.y)) << 16),
            (u32)__half_as_ushort(__float2half_rn(v.z)) | ((u32)__half_as_ushort(__float2half_rn(v.w)) << 16));
    }
}

// -------- tensor-core GEMM (fp16 2-term: Ah*Bh + Al*Bh; K32 3-stage ring) --------
#define KC      32
#define RSTRIDE 40
#define TILE_E  (128 * RSTRIDE)
#define TILE_B  (TILE_E * 2)
#define STAGE_B (3 * TILE_B)
#define NSTAGE  3
#define SMEM_BYTES (NSTAGE * STAGE_B)

template <int MODE>
__global__ __launch_bounds__(256)
void gemm_mma(const float* __restrict__ bias, float* __restrict__ out) {
    extern __shared__ __half sm[];

    const __half* Ah = MODE ? g_ahi : g_xhi;
    const __half* Al = MODE ? g_alo : g_xlo;
    const __half* Bh = MODE ? g_wphi : g_wqhi;

    const int tid  = threadIdx.x;
    const int warp = tid >> 5;
    const int lane = tid & 31;
    const int g    = lane >> 2;
    const int t4   = lane & 3;
    const int wm   = warp >> 2;
    const int wn   = warp & 3;

    const int    o0 = blockIdx.x * 128;
    const size_t m0 = (size_t)blockIdx.y * 128;

    const u32 smem_base = smem_u32(sm);

    const int row0 = tid >> 2;
    const int row1 = row0 + 64;
    const int seg  = (tid & 3) * 8;

    const __half* gA0h = Ah + (m0 + row0) * 256 + seg;
    const __half* gA1h = Ah + (m0 + row1) * 256 + seg;
    const __half* gA0l = Al + (m0 + row0) * 256 + seg;
    const __half* gA1l = Al + (m0 + row1) * 256 + seg;
    const __half* gB0h = Bh + (size_t)(o0 + row0) * 256 + seg;
    const __half* gB1h = Bh + (size_t)(o0 + row1) * 256 + seg;

    const u32 s0b = (u32)(row0 * RSTRIDE + seg) * 2;
    const u32 s1b = (u32)(row1 * RSTRIDE + seg) * 2;

    const int q3 = (lane >> 3) & 1;
    const int q4 = (lane >> 4) & 1;
    const int r8 = lane & 7;
    const u32 offA  = 0 * TILE_B + (u32)(((wm * 64 + q3 * 8 + r8) * RSTRIDE) + q4 * 8) * 2;
    const u32 offB0 = 2 * TILE_B + (u32)(((wn * 32 + 0 * 16 + q4 * 8 + r8) * RSTRIDE) + q3 * 8) * 2;
    const u32 offB1 = 2 * TILE_B + (u32)(((wn * 32 + 1 * 16 + q4 * 8 + r8) * RSTRIDE) + q3 * 8) * 2;

    float acc[4][4][4];
#pragma unroll
    for (int a = 0; a < 4; ++a)
#pragma unroll
        for (int b = 0; b < 4; ++b)
#pragma unroll
            for (int c = 0; c < 4; ++c) acc[a][b][c] = 0.f;

#define ISSUE_STAGE(stg, kb) do {                                      \
        const u32 nx = smem_base + (u32)(stg) * STAGE_B;               \
        CP_ASYNC16(nx + 0 * TILE_B + s0b, gA0h + (kb));                \
        CP_ASYNC16(nx + 0 * TILE_B + s1b, gA1h + (kb));                \
        CP_ASYNC16(nx + 1 * TILE_B + s0b, gA0l + (kb));                \
        CP_ASYNC16(nx + 1 * TILE_B + s1b, gA1l + (kb));                \
        CP_ASYNC16(nx + 2 * TILE_B + s0b, gB0h + (kb));                \
        CP_ASYNC16(nx + 2 * TILE_B + s1b, gB1h + (kb));                \
        CP_COMMIT();                                                   \
    } while (0)

    ISSUE_STAGE(0, 0);
    ISSUE_STAGE(1, KC);

    int cur = 0;
#pragma unroll 1
    for (int kc = 0; kc < 8; ++kc) {
        if (kc < 7) CP_WAITG(1);
        else        CP_WAITG(0);
        __syncthreads();

        if (kc + 2 < 8) {
            int nxt = cur + 2; if (nxt >= 3) nxt -= 3;
            ISSUE_STAGE(nxt, (kc + 2) * KC);
        }

        const u32 stb = smem_base + (u32)cur * STAGE_B;
#pragma unroll
        for (int ks = 0; ks < 2; ++ks) {
            const u32 kso = (u32)(ks * 32);
            u32 bh[4][2];
            LDSM_X4(bh[0][0], bh[0][1], bh[1][0], bh[1][1], stb + offB0 + kso);
            LDSM_X4(bh[2][0], bh[2][1], bh[3][0], bh[3][1], stb + offB1 + kso);
#pragma unroll
            for (int mi = 0; mi < 4; ++mi) {
                const u32 ao = stb + offA + (u32)(mi * 16 * RSTRIDE * 2) + kso;
                u32 ah0, ah1, ah2, ah3, al0, al1, al2, al3;
                LDSM_X4(ah0, ah1, ah2, ah3, ao);
                LDSM_X4(al0, al1, al2, al3, ao + TILE_B);
#pragma unroll
                for (int ni = 0; ni < 4; ++ni) {
                    mma16816(acc[mi][ni], ah0, ah1, ah2, ah3, bh[ni][0], bh[ni][1]);
                    mma16816(acc[mi][ni], al0, al1, al2, al3, bh[ni][0], bh[ni][1]);
                }
            }
        }
        if (++cur == 3) cur = 0;
    }
#undef ISSUE_STAGE

    // ---- epilogue ----
#pragma unroll
    for (int mi = 0; mi < 4; ++mi) {
        const int r0 = (int)m0 + wm * 64 + mi * 16 + g;
        const int r1 = r0 + 8;
#pragma unroll
        for (int ni = 0; ni < 4; ++ni) {
            const int c = o0 + wn * 32 + ni * 8 + 2 * t4;
            const float b0 = bias[c], b1 = bias[c + 1];
            float v00 = acc[mi][ni][0] + b0, v01 = acc[mi][ni][1] + b1;
            float v10 = acc[mi][ni][2] + b0, v11 = acc[mi][ni][3] + b1;
            if (MODE == 0) {
                // write q/k/v directly as fp16 hi/lo planes into g_qkv storage
                const int which = c >> 8;           // 0=q,1=k,2=v
                const int head  = (c >> 5) & 7;
                const int d     = c & 31;
                const int phi = (which == 0) ? 0 : (which == 1 ? 2 : 3);
                const int plo = (which == 0) ? 1 : (which == 1 ? -1 : 4);
                __half* qk = (__half*)g_qkv;
#pragma unroll
                for (int rr = 0; rr < 2; ++rr) {
                    const int m = rr ? r1 : r0;
                    const int bwin = m / NTOK;
                    const int n = m - bwin * NTOK;
                    const float y0 = rr ? v10 : v00;
                    const float y1 = rr ? v11 : v01;
                    unsigned short h0, l0, h1, l1;
                    split_h(y0, h0, l0);
                    split_h(y1, h1, l1);
                    const size_t idx = (((size_t)bwin * NH + head) * NTOK + n) * HD + d;
                    *(u32*)(qk + (size_t)phi * QKV_S + idx) = (u32)h0 | ((u32)h1 << 16);
                    if (plo >= 0)
                        *(u32*)(qk + (size_t)plo * QKV_S + idx) = (u32)l0 | ((u32)l1 << 16);
                }
            } else {
                *(float2*)(out + (size_t)r0 * 256 + c) = make_float2(v00, v01);
                *(float2*)(out + (size_t)r1 * 256 + c) = make_float2(v10, v11);
            }
        }
    }
}

// ---------------- tensor-core fused window attention ----------------
// One CTA (128 thr, 4 warps) per (window, head).
// S padded to 64x64: Q/K/V rows >=49 zero; cols >=49 masked by -1e30 bias.
#define APAD 40          /* fp16 elements per smem row (80 B, conflict-free) */
#define PLANE_B (64 * APAD * 2)   /* 5120 B */

__global__ __launch_bounds__(128)
void attn_tc() {
    __shared__ __align__(16) __half sp[5][64 * APAD];   // qh, ql, kh, vh, vl
    __shared__ float sbias[64][65];                     // full 64x64 + pad col

    const int tid  = threadIdx.x;
    const int warp = tid >> 5;
    const int lane = tid & 31;
    const int g    = lane >> 2;
    const int t4   = lane & 3;
    const int q3   = (lane >> 3) & 1;
    const int q4   = (lane >> 4) & 1;
    const int r8   = lane & 7;

    const int bh   = blockIdx.x;
    const int bwin = bh >> 3;
    const int h    = bh & 7;

    // zero pad rows 49..63 (cols 0..31) of all 5 planes
    for (int i = tid; i < 75; i += 128) {
        const int p = i / 15, r = 49 + (i % 15);
        uint4* dst = (uint4*)(sp[p] + r * APAD);
        dst[0] = make_uint4(0, 0, 0, 0);
        dst[1] = make_uint4(0, 0, 0, 0);
        dst[2] = make_uint4(0, 0, 0, 0);
        dst[3] = make_uint4(0, 0, 0, 0);
    }
    // bias (+mask) into smem: full 64x64 coverage
    {
        const float* bb = g_bias + h * (NTOK * NTOK);
        for (int i = tid; i < 64 * 64; i += 128) {
            const int r = i >> 6, c = i & 63;
            sbias[r][c] = (r < NTOK && c < NTOK) ? bb[r * NTOK + c] : -1e30f;
        }
    }
    // load q/k/v planes (fp16, contiguous 49x32 per plane)
    {
        const __half* qk = (const __half*)g_qkv;
        const size_t base = (size_t)bh * (NTOK * HD);
        for (int i = tid; i < 5 * 196; i += 128) {
            const int p = i / 196, seg = i - p * 196;
            const int row = seg >> 2, c8 = seg & 3;
            uint4 v = *(const uint4*)(qk + (size_t)p * QKV_S + base + (size_t)seg * 8);
            *(uint4*)(sp[p] + row * APAD + c8 * 8) = v;
        }
    }
    __syncthreads();

    const u32 smem0 = smem_u32(sp);
    const u32 pQH = smem0 + 0 * PLANE_B;
    const u32 pQL = smem0 + 1 * PLANE_B;
    const u32 pKH = smem0 + 2 * PLANE_B;
    const u32 pVH = smem0 + 3 * PLANE_B;
    const u32 pVL = smem0 + 4 * PLANE_B;

    // lane-relative ldmatrix offsets (bytes)
    const u32 aoff = (u32)(((16 * warp + q3 * 8 + r8) * APAD + q4 * 8) * 2);
    const u32 boff = (u32)(((q4 * 8 + r8) * APAD + q3 * 8) * 2);
    const u32 voff = (u32)(((q3 * 8 + r8) * APAD + q4 * 8) * 2);

    // ---- S = Q K^T (2-term), 16 rows per warp x 64 cols ----
    float sc[8][4];
#pragma unroll
    for (int j = 0; j < 8; ++j)
#pragma unroll
        for (int e = 0; e < 4; ++e) sc[j][e] = 0.f;

#pragma unroll
    for (int ks = 0; ks < 2; ++ks) {
        u32 qh0, qh1, qh2, qh3, ql0, ql1, ql2, ql3;
        LDSM_X4(qh0, qh1, qh2, qh3, pQH + aoff + (u32)(ks * 32));
        LDSM_X4(ql0, ql1, ql2, ql3, pQL + aoff + (u32)(ks * 32));
#pragma unroll
        for (int j4 = 0; j4 < 4; ++j4) {
            u32 b00, b01, b10, b11;
            LDSM_X4(b00, b01, b10, b11,
                    pKH + boff + (u32)((j4 * 16 * APAD + ks * 16) * 2));
            mma16816(sc[2 * j4],     qh0, qh1, qh2, qh3, b00, b01);
            mma16816(sc[2 * j4],     ql0, ql1, ql2, ql3, b00, b01);
            mma16816(sc[2 * j4 + 1], qh0, qh1, qh2, qh3, b10, b11);
            mma16816(sc[2 * j4 + 1], ql0, ql1, ql2, ql3, b10, b11);
        }
    }

    // ---- softmax in registers ----
    const float scale = 0.17677669529663687f;
    const int row0 = 16 * warp + g;
    const int row1 = row0 + 8;

    float mx0 = -1e30f, mx1 = -1e30f;
#pragma unroll
    for (int j = 0; j < 8; ++j) {
        const int col = 8 * j + 2 * t4;
        sc[j][0] = sc[j][0] * scale + sbias[row0][col];
        sc[j][1] = sc[j][1] * scale + sbias[row0][col + 1];
        sc[j][2] = sc[j][2] * scale + sbias[row1][col];
        sc[j][3] = sc[j][3] * scale + sbias[row1][col + 1];
        mx0 = fmaxf(mx0, fmaxf(sc[j][0], sc[j][1]));
        mx1 = fmaxf(mx1, fmaxf(sc[j][2], sc[j][3]));
    }
    mx0 = fmaxf(mx0, __shfl_xor_sync(0xffffffffu, mx0, 1));
    mx0 = fmaxf(mx0, __shfl_xor_sync(0xffffffffu, mx0, 2));
    mx1 = fmaxf(mx1, __shfl_xor_sync(0xffffffffu, mx1, 1));
    mx1 = fmaxf(mx1, __shfl_xor_sync(0xffffffffu, mx1, 2));

    float s0 = 0.f, s1 = 0.f;
    u32 ph[8][2], pl[8][2];
#pragma unroll
    for (int j = 0; j < 8; ++j) {
        const float e0 = __expf(sc[j][0] - mx0);
        const float e1 = __expf(sc[j][1] - mx0);
        const float e2 = __expf(sc[j][2] - mx1);
        const float e3 = __expf(sc[j][3] - mx1);
        s0 += e0 + e1;
        s1 += e2 + e3;
        unsigned short h0, l0, h1, l1, h2, l2, h3, l3;
        split_h(e0, h0, l0); split_h(e1, h1, l1);
        split_h(e2, h2, l2); split_h(e3, h3, l3);
        ph[j][0] = (u32)h0 | ((u32)h1 << 16);
        ph[j][1] = (u32)h2 | ((u32)h3 << 16);
        pl[j][0] = (u32)l0 | ((u32)l1 << 16);
        pl[j][1] = (u32)l2 | ((u32)l3 << 16);
    }
    s0 += __shfl_xor_sync(0xffffffffu, s0, 1);
    s0 += __shfl_xor_sync(0xffffffffu, s0, 2);
    s1 += __shfl_xor_sync(0xffffffffu, s1, 1);
    s1 += __shfl_xor_sync(0xffffffffu, s1, 2);
    const float inv0 = 1.f / s0;
    const float inv1 = 1.f / s1;

    // ---- O = P~ V (3-term: PhVh + PlVh + PhVl) ----
    float o[4][4];
#pragma unroll
    for (int n = 0; n < 4; ++n)
#pragma unroll
        for (int e = 0; e < 4; ++e) o[n][e] = 0.f;

#pragma unroll
    for (int kt = 0; kt < 4; ++kt) {
        u32 vh[4][2], vl[4][2];
        LDSM_X4T(vh[0][0], vh[0][1], vh[1][0], vh[1][1],
                 pVH + voff + (u32)((kt * 16 * APAD + 0) * 2));
        LDSM_X4T(vh[2][0], vh[2][1], vh[3][0], vh[3][1],
                 pVH + voff + (u32)((kt * 16 * APAD + 16) * 2));
        LDSM_X4T(vl[0][0], vl[0][1], vl[1][0], vl[1][1],
                 pVL + voff + (u32)((kt * 16 * APAD + 0) * 2));
        LDSM_X4T(vl[2][0], vl[2][1], vl[3][0], vl[3][1],
                 pVL + voff + (u32)((kt * 16 * APAD + 16) * 2));
        const u32 a0 = ph[2 * kt][0],     a1 = ph[2 * kt][1];
        const u32 a2 = ph[2 * kt + 1][0], a3 = ph[2 * kt + 1][1];
        const u32 c0 = pl[2 * kt][0],     c1 = pl[2 * kt][1];
        const u32 c2 = pl[2 * kt + 1][0], c3 = pl[2 * kt + 1][1];
#pragma unroll
        for (int n = 0; n < 4; ++n) {
            mma16816(o[n], a0, a1, a2, a3, vh[n][0], vh[n][1]);
            mma16816(o[n], c0, c1, c2, c3, vh[n][0], vh[n][1]);
            mma16816(o[n], a0, a1, a2, a3, vl[n][0], vl[n][1]);
        }
    }

    // ---- epilogue: divide by sum, split hi/lo, store ----
    if (row0 < NTOK) {
        const size_t rb = ((size_t)bwin * NTOK + row0) * 256 + h * 32;
#pragma unroll
        for (int n = 0; n < 4; ++n) {
            const int col = 8 * n + 2 * t4;
            unsigned short h0, l0, h1, l1;
            split_h(o[n][0] * inv0, h0, l0);
            split_h(o[n][1] * inv0, h1, l1);
            *(u32*)(g_ahi + rb + col) = (u32)h0 | ((u32)h1 << 16);
            *(u32*)(g_alo + rb + col) = (u32)l0 | ((u32)l1 << 16);
        }
    }
    if (row1 < NTOK) {
        const size_t rb = ((size_t)bwin * NTOK + row1) * 256 + h * 32;
#pragma unroll
        for (int n = 0; n < 4; ++n) {
            const int col = 8 * n + 2 * t4;
            unsigned short h0, l0, h1, l1;
            split_h(o[n][2] * inv1, h0, l0);
            split_h(o[n][3] * inv1, h1, l1);
            *(u32*)(g_ahi + rb + col) = (u32)h0 | ((u32)h1 << 16);
            *(u32*)(g_alo + rb + col) = (u32)l0 | ((u32)l1 << 16);
        }
    }
}

// ---------------- launch ----------------
extern "C" void kernel_launch(void* const* d_in, const int* in_sizes, int n_in,
                              void* d_out, int out_size) {
    const float* x      = (const float*)d_in[0];
    const float* qkv_w  = (const float*)d_in[1];
    const float* qkv_b  = (const float*)d_in[2];
    const float* proj_w = (const float*)d_in[3];
    const float* proj_b = (const float*)d_in[4];
    const float* table  = (const float*)d_in[5];
    const int*   rel    = (const int*)d_in[6];
    float* out = (float*)d_out;

    static int smem_set = 0;
    if (!smem_set) {
        cudaFuncSetAttribute(gemm_mma<0>, cudaFuncAttributeMaxDynamicSharedMemorySize, SMEM_BYTES);
        cudaFuncSetAttribute(gemm_mma<1>, cudaFuncAttributeMaxDynamicSharedMemorySize, SMEM_BYTES);
        smem_set = 1;
    }

    bias_kernel<<<(NH * NTOK * NTOK + 255) / 256, 256>>>(table, rel);
    conv_x<<<(int)(((size_t)MTOT * DIM / 4 + 255) / 256), 256>>>(x);
    conv_w<<<((768 + 256) * 256 / 4 + 255) / 256, 256>>>(qkv_w, proj_w);
    gemm_mma<0><<<dim3(6, MTOT / 128), 256, SMEM_BYTES>>>(qkv_b, nullptr);
    attn_tc<<<BWIN * NH, 128>>>();
    gemm_mma<1><<<dim3(2, MTOT / 128), 256, SMEM_BYTES>>>(proj_b, out);
}

// round 12
// speedup vs baseline: 1.0801x; 1.0801x over previous
#include <cuda_runtime.h>
#include <cuda_fp16.h>
#include <cstdint>

#define BWIN 4096
#define NTOK 49
#define DIM  256
#define NH   8
#define HD   32
#define MTOT (BWIN * NTOK)            /* 200704 */
#define QKV_S (BWIN * NH * NTOK * HD) /* 51380224 */

typedef unsigned long long u64;
typedef unsigned int u32;

// ---------------- device scratch (allocation-free) ----------------
__device__ float g_qkv[3ULL * QKV_S];                       // fp32 [3][B][H][N][hd]
__device__ float g_bias[NH * NTOK * NTOK];                  // [H][N][N]
__device__ __align__(16) __half g_xhi[(size_t)MTOT * DIM];
__device__ __align__(16) __half g_xlo[(size_t)MTOT * DIM];
__device__ __align__(16) __half g_ahi[(size_t)MTOT * DIM];
__device__ __align__(16) __half g_alo[(size_t)MTOT * DIM];
__device__ __align__(16) __half g_wqhi[768 * 256];
__device__ __align__(16) __half g_wphi[256 * 256];

// ---------------- helpers ----------------
__device__ __forceinline__ u64 f2fma(u64 a, u64 b, u64 c) {
    u64 d;
    asm("fma.rn.f32x2 %0, %1, %2, %3;" : "=l"(d) : "l"(a), "l"(b), "l"(c));
    return d;
}
__device__ __forceinline__ u64 dup32(float x) {
    u64 d;
    asm("mov.b64 %0, {%1, %1};" : "=l"(d) : "r"(__float_as_uint(x)));
    return d;
}
__device__ __forceinline__ void split_h(float x, unsigned short& h, unsigned short& l) {
    __half hb = __float2half_rn(x);
    float r = x - __half2float(hb);
    __half lb = __float2half_rn(r);
    h = __half_as_ushort(hb);
    l = __half_as_ushort(lb);
}
__device__ __forceinline__ u32 smem_u32(const void* p) {
    u32 a;
    asm("{ .reg .u64 t; cvta.to.shared.u64 t, %1; cvt.u32.u64 %0, t; }" : "=r"(a) : "l"(p));
    return a;
}

__device__ __forceinline__ void mma16816(float* d, u32 a0, u32 a1, u32 a2, u32 a3,
                                         u32 b0, u32 b1) {
    asm volatile(
        "mma.sync.aligned.m16n8k16.row.col.f32.f16.f16.f32 "
        "{%0,%1,%2,%3}, {%4,%5,%6,%7}, {%8,%9}, {%0,%1,%2,%3};"
        : "+f"(d[0]), "+f"(d[1]), "+f"(d[2]), "+f"(d[3])
        : "r"(a0), "r"(a1), "r"(a2), "r"(a3), "r"(b0), "r"(b1));
}

#define LDSM_X4(r0, r1, r2, r3, addr) \
    asm volatile("ldmatrix.sync.aligned.m8n8.x4.shared.b16 {%0,%1,%2,%3}, [%4];" \
        : "=r"(r0), "=r"(r1), "=r"(r2), "=r"(r3) : "r"(addr))

#define CP_ASYNC16(s, g) \
    asm volatile("cp.async.cg.shared.global [%0], [%1], 16;" :: "r"(s), "l"(g))
#define CP_COMMIT() asm volatile("cp.async.commit_group;" ::: "memory")
#define CP_WAITG(n) asm volatile("cp.async.wait_group %0;" :: "n"(n) : "memory")

// ---------------- kernel: bias gather ----------------
__global__ void bias_kernel(const float* __restrict__ table, const int* __restrict__ rel) {
    int idx = blockIdx.x * 256 + threadIdx.x;
    if (idx < NH * NTOK * NTOK) {
        int h = idx / (NTOK * NTOK);
        int nm = idx - h * (NTOK * NTOK);
        g_bias[idx] = table[rel[nm] * NH + h];
    }
}

// ---------------- kernels: fp32 -> fp16 hi/lo ----------------
__global__ void conv_x(const float* __restrict__ x) {
    size_t i = (size_t)blockIdx.x * 256 + threadIdx.x;
    if (i < (size_t)MTOT * DIM / 4) {
        float4 v = ((const float4*)x)[i];
        unsigned short h0, h1, h2, h3, l0, l1, l2, l3;
        split_h(v.x, h0, l0); split_h(v.y, h1, l1);
        split_h(v.z, h2, l2); split_h(v.w, h3, l3);
        ((uint2*)g_xhi)[i] = make_uint2((u32)h0 | ((u32)h1 << 16), (u32)h2 | ((u32)h3 << 16));
        ((uint2*)g_xlo)[i] = make_uint2((u32)l0 | ((u32)l1 << 16), (u32)l2 | ((u32)l3 << 16));
    }
}
__global__ void conv_w(const float* __restrict__ wq, const float* __restrict__ wp) {
    int i = blockIdx.x * 256 + threadIdx.x;
    const int nq4 = 768 * 256 / 4;
    const int np4 = 256 * 256 / 4;
    if (i < nq4) {
        float4 v = ((const float4*)wq)[i];
        ((uint2*)g_wqhi)[i] = make_uint2(
            (u32)__half_as_ushort(__float2half_rn(v.x)) | ((u32)__half_as_ushort(__float2half_rn(v.y)) << 16),
            (u32)__half_as_ushort(__float2half_rn(v.z)) | ((u32)__half_as_ushort(__float2half_rn(v.w)) << 16));
    } else if (i < nq4 + np4) {
        int j = i - nq4;
        float4 v = ((const float4*)wp)[j];
        ((uint2*)g_wphi)[j] = make_uint2(
            (u32)__half_as_ushort(__float2half_rn(v.x)) | ((u32)__half_as_ushort(__float2half_rn(v.y)) << 16),
            (u32)__half_as_ushort(__float2half_rn(v.z)) | ((u32)__half_as_ushort(__float2half_rn(v.w)) << 16));
    }
}

// -------- tensor-core GEMM (fp16 2-term: Ah*Bh + Al*Bh; K32 3-stage ring) --------
#define KC      32
#define RSTRIDE 40
#define TILE_E  (128 * RSTRIDE)
#define TILE_B  (TILE_E * 2)
#define STAGE_B (3 * TILE_B)
#define NSTAGE  3
#define SMEM_BYTES (NSTAGE * STAGE_B)

template <int MODE>
__global__ __launch_bounds__(256)
void gemm_mma(const float* __restrict__ bias, float* __restrict__ out) {
    extern __shared__ __half sm[];

    const __half* Ah = MODE ? g_ahi : g_xhi;
    const __half* Al = MODE ? g_alo : g_xlo;
    const __half* Bh = MODE ? g_wphi : g_wqhi;

    const int tid  = threadIdx.x;
    const int warp = tid >> 5;
    const int lane = tid & 31;
    const int g    = lane >> 2;
    const int t4   = lane & 3;
    const int wm   = warp >> 2;
    const int wn   = warp & 3;

    const int    o0 = blockIdx.x * 128;
    const size_t m0 = (size_t)blockIdx.y * 128;

    const u32 smem_base = smem_u32(sm);

    const int row0 = tid >> 2;
    const int row1 = row0 + 64;
    const int seg  = (tid & 3) * 8;

    const __half* gA0h = Ah + (m0 + row0) * 256 + seg;
    const __half* gA1h = Ah + (m0 + row1) * 256 + seg;
    const __half* gA0l = Al + (m0 + row0) * 256 + seg;
    const __half* gA1l = Al + (m0 + row1) * 256 + seg;
    const __half* gB0h = Bh + (size_t)(o0 + row0) * 256 + seg;
    const __half* gB1h = Bh + (size_t)(o0 + row1) * 256 + seg;

    const u32 s0b = (u32)(row0 * RSTRIDE + seg) * 2;
    const u32 s1b = (u32)(row1 * RSTRIDE + seg) * 2;

    const int q3 = (lane >> 3) & 1;
    const int q4 = (lane >> 4) & 1;
    const int r8 = lane & 7;
    const u32 offA  = 0 * TILE_B + (u32)(((wm * 64 + q3 * 8 + r8) * RSTRIDE) + q4 * 8) * 2;
    const u32 offB0 = 2 * TILE_B + (u32)(((wn * 32 + 0 * 16 + q4 * 8 + r8) * RSTRIDE) + q3 * 8) * 2;
    const u32 offB1 = 2 * TILE_B + (u32)(((wn * 32 + 1 * 16 + q4 * 8 + r8) * RSTRIDE) + q3 * 8) * 2;

    float acc[4][4][4];
#pragma unroll
    for (int a = 0; a < 4; ++a)
#pragma unroll
        for (int b = 0; b < 4; ++b)
#pragma unroll
            for (int c = 0; c < 4; ++c) acc[a][b][c] = 0.f;

#define ISSUE_STAGE(stg, kb) do {                                      \
        const u32 nx = smem_base + (u32)(stg) * STAGE_B;               \
        CP_ASYNC16(nx + 0 * TILE_B + s0b, gA0h + (kb));                \
        CP_ASYNC16(nx + 0 * TILE_B + s1b, gA1h + (kb));                \
        CP_ASYNC16(nx + 1 * TILE_B + s0b, gA0l + (kb));                \
        CP_ASYNC16(nx + 1 * TILE_B + s1b, gA1l + (kb));                \
        CP_ASYNC16(nx + 2 * TILE_B + s0b, gB0h + (kb));                \
        CP_ASYNC16(nx + 2 * TILE_B + s1b, gB1h + (kb));                \
        CP_COMMIT();                                                   \
    } while (0)

    ISSUE_STAGE(0, 0);
    ISSUE_STAGE(1, KC);

    int cur = 0;
#pragma unroll 1
    for (int kc = 0; kc < 8; ++kc) {
        if (kc < 7) CP_WAITG(1);
        else        CP_WAITG(0);
        __syncthreads();

        if (kc + 2 < 8) {
            int nxt = cur + 2; if (nxt >= 3) nxt -= 3;
            ISSUE_STAGE(nxt, (kc + 2) * KC);
        }

        const u32 stb = smem_base + (u32)cur * STAGE_B;
#pragma unroll
        for (int ks = 0; ks < 2; ++ks) {
            const u32 kso = (u32)(ks * 32);
            u32 bh[4][2];
            LDSM_X4(bh[0][0], bh[0][1], bh[1][0], bh[1][1], stb + offB0 + kso);
            LDSM_X4(bh[2][0], bh[2][1], bh[3][0], bh[3][1], stb + offB1 + kso);
#pragma unroll
            for (int mi = 0; mi < 4; ++mi) {
                const u32 ao = stb + offA + (u32)(mi * 16 * RSTRIDE * 2) + kso;
                u32 ah0, ah1, ah2, ah3, al0, al1, al2, al3;
                LDSM_X4(ah0, ah1, ah2, ah3, ao);
                LDSM_X4(al0, al1, al2, al3, ao + TILE_B);
#pragma unroll
                for (int ni = 0; ni < 4; ++ni) {
                    mma16816(acc[mi][ni], ah0, ah1, ah2, ah3, bh[ni][0], bh[ni][1]);
                    mma16816(acc[mi][ni], al0, al1, al2, al3, bh[ni][0], bh[ni][1]);
                }
            }
        }
        if (++cur == 3) cur = 0;
    }
#undef ISSUE_STAGE

    // ---- epilogue: bias add + store straight from registers ----
#pragma unroll
    for (int mi = 0; mi < 4; ++mi) {
        const int r0 = (int)m0 + wm * 64 + mi * 16 + g;
        const int r1 = r0 + 8;
#pragma unroll
        for (int ni = 0; ni < 4; ++ni) {
            const int c = o0 + wn * 32 + ni * 8 + 2 * t4;
            const float b0 = bias[c], b1 = bias[c + 1];
            float v00 = acc[mi][ni][0] + b0, v01 = acc[mi][ni][1] + b1;
            float v10 = acc[mi][ni][2] + b0, v11 = acc[mi][ni][3] + b1;
            if (MODE == 0) {
                const int which = c >> 8;
                const int head  = (c >> 5) & 7;
                const int d     = c & 31;
#pragma unroll
                for (int rr = 0; rr < 2; ++rr) {
                    const int m = rr ? r1 : r0;
                    const int bwin = m / NTOK;
                    const int n = m - bwin * NTOK;
                    float* dst = g_qkv + (size_t)which * QKV_S +
                        (((size_t)bwin * NH + head) * NTOK + n) * HD + d;
                    *(float2*)dst = rr ? make_float2(v10, v11) : make_float2(v00, v01);
                }
            } else {
                *(float2*)(out + (size_t)r0 * 256 + c) = make_float2(v00, v01);
                *(float2*)(out + (size_t)r1 * 256 + c) = make_float2(v10, v11);
            }
        }
    }
}

// ---------------- fused window attention (f32x2 register tiles) ----------------
// smem: 3 planes of 49x34 (q,k,v) = 20 KB; score matrix s ALIASES planes 0-1
// (sq/sk) after the QK read phase completes -> 20 KB total, ~9 CTAs/SM.
__global__ __launch_bounds__(64)
void attn_kernel() {
    __shared__ __align__(16) float pool[3][NTOK][34];
    float (*sq)[34] = pool[0];
    float (*sk)[34] = pool[1];
    float (*sv)[34] = pool[2];
    float (*s)[50]  = (float (*)[50])&pool[0][0][0];   // 2450 floats <= 2*1666

    const int tid = threadIdx.x;
    const int bh = blockIdx.x;
    const int bwin = bh >> 3;
    const int h = bh & 7;

    const size_t base = (size_t)bh * (NTOK * HD);
    const float4* q4 = (const float4*)(g_qkv + base);
    const float4* k4 = (const float4*)(g_qkv + (size_t)QKV_S + base);
    const float4* v4 = (const float4*)(g_qkv + 2ULL * QKV_S + base);

    for (int i = tid; i < NTOK * HD / 4; i += 64) {
        const int r = i >> 3, c = (i & 7) * 4;
        float4 a = q4[i];
        sq[r][c] = a.x; sq[r][c + 1] = a.y; sq[r][c + 2] = a.z; sq[r][c + 3] = a.w;
        float4 b = k4[i];
        sk[r][c] = b.x; sk[r][c + 1] = b.y; sk[r][c + 2] = b.z; sk[r][c + 3] = b.w;
        float4 d = v4[i];
        sv[r][c] = d.x; sv[r][c + 1] = d.y; sv[r][c + 2] = d.z; sv[r][c + 3] = d.w;
    }
    __syncthreads();

    // QK^T accumulate fully into registers (reads sq/sk only)
    u64 acc[7][7];
    int n0 = 0, m0 = 0;
    if (tid < 49) {
        const int ti = tid / 7, tj = tid - ti * 7;
        n0 = ti * 7; m0 = tj * 7;
#pragma unroll
        for (int r = 0; r < 7; ++r)
#pragma unroll
            for (int cc = 0; cc < 7; ++cc) acc[r][cc] = 0ull;
#pragma unroll
        for (int kk = 0; kk < 16; ++kk) {
            u64 qv[7], kv[7];
#pragma unroll
            for (int r = 0; r < 7; ++r) qv[r] = *(const u64*)&sq[n0 + r][2 * kk];
#pragma unroll
            for (int cc = 0; cc < 7; ++cc) kv[cc] = *(const u64*)&sk[m0 + cc][2 * kk];
#pragma unroll
            for (int r = 0; r < 7; ++r)
#pragma unroll
                for (int cc = 0; cc < 7; ++cc) acc[r][cc] = f2fma(qv[r], kv[cc], acc[r][cc]);
        }
    }
    __syncthreads();   // all sq/sk reads done before s (aliased) is written

    if (tid < 49) {
        const float scale = 0.17677669529663687f;
        const float* bb = g_bias + h * (NTOK * NTOK);
#pragma unroll
        for (int r = 0; r < 7; ++r)
#pragma unroll
            for (int cc = 0; cc < 7; ++cc) {
                const u64 a = acc[r][cc];
                const float lo = __uint_as_float((u32)(a & 0xffffffffull));
                const float hi = __uint_as_float((u32)(a >> 32));
                s[n0 + r][m0 + cc] = (lo + hi) * scale + bb[(n0 + r) * NTOK + m0 + cc];
            }
    }
    __syncthreads();

    if (tid < 49) {
        float mx = -1e30f;
#pragma unroll
        for (int c = 0; c < NTOK; ++c) mx = fmaxf(mx, s[tid][c]);
        float sum = 0.f;
#pragma unroll
        for (int c = 0; c < NTOK; ++c) {
            float e = __expf(s[tid][c] - mx);
            s[tid][c] = e;
            sum += e;
        }
        const float inv = 1.f / sum;
#pragma unroll
        for (int c = 0; c < NTOK; ++c) s[tid][c] *= inv;
    }
    __syncthreads();

    // P @ V: 56 threads (2 warps), 7(n) x 4(d) register tiles, f32x2 along d
    if (tid < 56) {
        const int ti = tid >> 3, tj = tid & 7;
        const int nn0 = ti * 7, d0 = tj * 4;
        u64 acc2[7][2];
#pragma unroll
        for (int r = 0; r < 7; ++r) { acc2[r][0] = 0ull; acc2[r][1] = 0ull; }
#pragma unroll 7
        for (int m = 0; m < NTOK; ++m) {
            const u64 v0 = *(const u64*)&sv[m][d0];
            const u64 v1 = *(const u64*)&sv[m][d0 + 2];
#pragma unroll
            for (int r = 0; r < 7; ++r) {
                const u64 sd = dup32(s[nn0 + r][m]);
                acc2[r][0] = f2fma(sd, v0, acc2[r][0]);
                acc2[r][1] = f2fma(sd, v1, acc2[r][1]);
            }
        }
#pragma unroll
        for (int r = 0; r < 7; ++r) {
            unsigned short hh[4], ll[4];
#pragma unroll
            for (int cc = 0; cc < 2; ++cc) {
                const u64 a = acc2[r][cc];
                split_h(__uint_as_float((u32)(a & 0xffffffffull)), hh[2 * cc], ll[2 * cc]);
                split_h(__uint_as_float((u32)(a >> 32)), hh[2 * cc + 1], ll[2 * cc + 1]);
            }
            uint2 vh = make_uint2((u32)hh[0] | ((u32)hh[1] << 16), (u32)hh[2] | ((u32)hh[3] << 16));
            uint2 vl = make_uint2((u32)ll[0] | ((u32)ll[1] << 16), (u32)ll[2] | ((u32)ll[3] << 16));
            const size_t off = ((size_t)bwin * NTOK + nn0 + r) * 256 + h * 32 + d0;
            *(uint2*)(g_ahi + off) = vh;
            *(uint2*)(g_alo + off) = vl;
        }
    }
}

// ---------------- launch ----------------
extern "C" void kernel_launch(void* const* d_in, const int* in_sizes, int n_in,
                              void* d_out, int out_size) {
    const float* x      = (const float*)d_in[0];
    const float* qkv_w  = (const float*)d_in[1];
    const float* qkv_b  = (const float*)d_in[2];
    const float* proj_w = (const float*)d_in[3];
    const float* proj_b = (const float*)d_in[4];
    const float* table  = (const float*)d_in[5];
    const int*   rel    = (const int*)d_in[6];
    float* out = (float*)d_out;

    static int smem_set = 0;
    if (!smem_set) {
        cudaFuncSetAttribute(gemm_mma<0>, cudaFuncAttributeMaxDynamicSharedMemorySize, SMEM_BYTES);
        cudaFuncSetAttribute(gemm_mma<1>, cudaFuncAttributeMaxDynamicSharedMemorySize, SMEM_BYTES);
        smem_set = 1;
    }

    bias_kernel<<<(NH * NTOK * NTOK + 255) / 256, 256>>>(table, rel);
    conv_x<<<(int)(((size_t)MTOT * DIM / 4 + 255) / 256), 256>>>(x);
    conv_w<<<((768 + 256) * 256 / 4 + 255) / 256, 256>>>(qkv_w, proj_w);
    gemm_mma<0><<<dim3(6, MTOT / 128), 256, SMEM_BYTES>>>(qkv_b, nullptr);
    attn_kernel<<<BWIN * NH, 64>>>();
    gemm_mma<1><<<dim3(2, MTOT / 128), 256, SMEM_BYTES>>>(proj_b, out);
}